// round 14
// baseline (speedup 1.0000x reference)
#include <cuda_runtime.h>
#include <math.h>
#include <stdint.h>

// ---------------------------------------------------------------------------
// HashEncoderHyFluid, R12 (final): R9 scheme — lane-pair cooperative gathers
// (2 lanes/query, x-pair corners coalesce into one L1tex wavefront) + 4-level
// batched coalesced float4 stores. Loop split into a dense part (levels 0..2)
// and a hashed part (3..15) to drop the per-level mode branch; host validates
// the mode pattern and falls back to the universal kernel if it ever differs.
// Kernel is at the measured wavefront floor: ~133 line-accesses/query at 93%
// L1tex utilization (structural ceiling; R9/R11 occupancy sweep both tie).
// ---------------------------------------------------------------------------

struct Level {
    float    rf0, rf1, rf2, rf3;   // res as float32
    unsigned s1, s2, s3;           // dense strides
    unsigned mask;                 // size-1 (hashed pow2)
    unsigned size;
    int      offset;               // float offset into hash_table
    int      mode;                 // 0 dense, 1 hash+mask, 2 hash+mod
};
struct KConfig { Level lv[16]; };

#define HPRIME1 2654435761u
#define HPRIME2 805459861u
#define HPRIME3 3674653429u

// ---- per-level bodies (this lane's x-corner; post-shfl result in a0,a1) ----

__device__ __forceinline__ void gather8(const float2* __restrict__ t2,
                                        const unsigned idx[8], const float wj[8],
                                        float wxs, unsigned amask,
                                        float& a0, float& a1)
{
    float s0 = 0.f, s1 = 0.f;
    #pragma unroll
    for (int k = 0; k < 8; ++k) {
        float2 f = __ldg(t2 + idx[k]);    // pair lanes hit the same 128B line
        s0 += wj[k] * f.x;
        s1 += wj[k] * f.y;
    }
    s0 *= wxs;
    s1 *= wxs;
    s0 += __shfl_xor_sync(amask, s0, 1);
    s1 += __shfl_xor_sync(amask, s1, 1);
    a0 = s0; a1 = s1;
}

__device__ __forceinline__ void frac_setup(const float4& X, const Level& L,
                                           unsigned xb,
                                           unsigned& cx, unsigned& cy,
                                           unsigned& cz, unsigned& ct,
                                           float wj[8], float& wxs)
{
    float px = X.x * L.rf0, py = X.y * L.rf1, pz = X.z * L.rf2, pt = X.w * L.rf3;
    float gx = floorf(px),  gy = floorf(py),  gz = floorf(pz),  gt = floorf(pt);
    float fx = px - gx,     fy = py - gy,     fz = pz - gz,     ft = pt - gt;
    cx = (unsigned)(int)gx; cy = (unsigned)(int)gy;
    cz = (unsigned)(int)gz; ct = (unsigned)(int)gt;

    wxs = xb ? fx : (1.f - fx);
    float wy0 = 1.f - fy, wz0 = 1.f - fz, wt0 = 1.f - ft;
    float wzt[4];
    wzt[0] = wz0 * wt0;  wzt[1] = fz * wt0;  wzt[2] = wz0 * ft;  wzt[3] = fz * ft;
    #pragma unroll
    for (int k = 0; k < 4; ++k) { wj[k] = wy0 * wzt[k]; wj[4 + k] = fy * wzt[k]; }
}

__device__ __forceinline__ void enc_dense(const float4& X, const Level& L,
                                          const float* __restrict__ tab,
                                          unsigned xb, unsigned amask,
                                          float& a0, float& a1)
{
    unsigned cx, cy, cz, ct; float wj[8], wxs;
    frac_setup(X, L, xb, cx, cy, cz, ct, wj, wxs);

    unsigned idx[8];
    unsigned base0 = (cx + xb) + cy * L.s1 + cz * L.s2 + ct * L.s3;
    idx[0] = base0;
    idx[1] = base0 + L.s2;
    idx[2] = base0 + L.s3;
    idx[3] = base0 + L.s2 + L.s3;
    #pragma unroll
    for (int k = 0; k < 4; ++k) idx[4 + k] = idx[k] + L.s1;

    const float2* t2 = reinterpret_cast<const float2*>(tab) + (L.offset >> 1);
    gather8(t2, idx, wj, wxs, amask, a0, a1);
}

__device__ __forceinline__ void enc_hash(const float4& X, const Level& L,
                                         const float* __restrict__ tab,
                                         unsigned xb, unsigned amask,
                                         float& a0, float& a1)
{
    unsigned cx, cy, cz, ct; float wj[8], wxs;
    frac_setup(X, L, xb, cx, cy, cz, ct, wj, wxs);

    unsigned bx = cx + xb;
    unsigned hy = cy * HPRIME1, hz = cz * HPRIME2, ht = ct * HPRIME3;
    unsigned msk = L.mask;
    unsigned rzt[4] = { hz ^ ht, (hz + HPRIME2) ^ ht,
                        hz ^ (ht + HPRIME3), (hz + HPRIME2) ^ (ht + HPRIME3) };
    unsigned idx[8];
    #pragma unroll
    for (int k = 0; k < 4; ++k) {
        idx[k]     = (bx ^ hy             ^ rzt[k]) & msk;
        idx[4 + k] = (bx ^ (hy + HPRIME1) ^ rzt[k]) & msk;
    }

    const float2* t2 = reinterpret_cast<const float2*>(tab) + (L.offset >> 1);
    gather8(t2, idx, wj, wxs, amask, a0, a1);
}

// universal per-level (any mode) — fallback kernel only
__device__ __forceinline__ void enc_any(const float4& X, const Level& L,
                                        const float* __restrict__ tab,
                                        unsigned xb, unsigned amask,
                                        float& a0, float& a1)
{
    if (L.mode == 0) { enc_dense(X, L, tab, xb, amask, a0, a1); return; }
    if (L.mode == 1) { enc_hash (X, L, tab, xb, amask, a0, a1); return; }
    unsigned cx, cy, cz, ct; float wj[8], wxs;
    frac_setup(X, L, xb, cx, cy, cz, ct, wj, wxs);
    unsigned bx = cx + xb;
    unsigned hy = cy * HPRIME1, hz = cz * HPRIME2, ht = ct * HPRIME3;
    unsigned sz = L.size;
    unsigned rzt[4] = { hz ^ ht, (hz + HPRIME2) ^ ht,
                        hz ^ (ht + HPRIME3), (hz + HPRIME2) ^ (ht + HPRIME3) };
    unsigned idx[8];
    #pragma unroll
    for (int k = 0; k < 4; ++k) {
        idx[k]     = (bx ^ hy             ^ rzt[k]) % sz;
        idx[4 + k] = (bx ^ (hy + HPRIME1) ^ rzt[k]) % sz;
    }
    const float2* t2 = reinterpret_cast<const float2*>(tab) + (L.offset >> 1);
    gather8(t2, idx, wj, wxs, amask, a0, a1);
}

// ---- result buffering: 4-level groups -> coalesced float4 row stores ----
// group g: even lane buffers levels 4g,4g+1 -> row slot 2g; odd lane buffers
// levels 4g+2,4g+3 -> slot 2g+1. Pair lanes store into the same 128B row.

struct GroupBuf {
    float r0, r1, r2, r3;
    __device__ __forceinline__ void put(int j, unsigned xb, float a0, float a1) {
        bool mine = xb ? (j >= 2) : (j < 2);
        int  lo   = xb ? (j - 2) : j;
        if (mine) {
            if (lo == 0) { r0 = a0; r1 = a1; }
            else         { r2 = a0; r3 = a1; }
        }
    }
};

// NDENSE levels (0..NDENSE-1) dense, rest hashed pow2.
__global__ __launch_bounds__(256)
void hashenc_split_kernel(const float4* __restrict__ xyzt,
                          const float*  __restrict__ tab,
                          float*        __restrict__ out,
                          KConfig cfg, int n, int ndense)
{
    int tid = blockIdx.x * 256 + threadIdx.x;
    int q = tid >> 1;
    if (q >= n) return;
    const unsigned xb = (unsigned)(tid & 1);
    const unsigned amask = __activemask();

    float4 X = __ldg(&xyzt[q]);
    float4* orow = reinterpret_cast<float4*>(out + (size_t)q * 32);

    GroupBuf buf;
    // dense levels (uniform trip count; ndense < 4 so all in group 0)
    #pragma unroll 1
    for (int s = 0; s < ndense; ++s) {
        float a0, a1;
        enc_dense(X, cfg.lv[s], tab, xb, amask, a0, a1);
        buf.put(s & 3, xb, a0, a1);
    }
    // hashed levels
    #pragma unroll 1
    for (int s = ndense; s < 16; ++s) {
        float a0, a1;
        enc_hash(X, cfg.lv[s], tab, xb, amask, a0, a1);
        int j = s & 3;
        buf.put(j, xb, a0, a1);
        if (j == 3)
            orow[((s >> 2) << 1) + xb] = make_float4(buf.r0, buf.r1, buf.r2, buf.r3);
    }
}

// fallback: any mode pattern (R9 behavior)
__global__ __launch_bounds__(256)
void hashenc_kernel(const float4* __restrict__ xyzt,
                    const float*  __restrict__ tab,
                    float*        __restrict__ out,
                    KConfig cfg, int n)
{
    int tid = blockIdx.x * 256 + threadIdx.x;
    int q = tid >> 1;
    if (q >= n) return;
    const unsigned xb = (unsigned)(tid & 1);
    const unsigned amask = __activemask();

    float4 X = __ldg(&xyzt[q]);
    float4* orow = reinterpret_cast<float4*>(out + (size_t)q * 32);

    GroupBuf buf;
    #pragma unroll 1
    for (int s = 0; s < 16; ++s) {
        float a0, a1;
        enc_any(X, cfg.lv[s], tab, xb, amask, a0, a1);
        int j = s & 3;
        buf.put(j, xb, a0, a1);
        if (j == 3)
            orow[((s >> 2) << 1) + xb] = make_float4(buf.r0, buf.r1, buf.r2, buf.r3);
    }
}

// ---------------------------------------------------------------------------
// Host-side config: mirrors reference build_config() op-for-op in float64.
// ---------------------------------------------------------------------------
static KConfig build_cfg_host()
{
    const double minr[4] = {16.0, 16.0, 16.0, 16.0};
    const double maxr[4] = {256.0, 256.0, 256.0, 128.0};
    const long long MAXP = 524288; // 2^19

    double b[4];
    for (int d = 0; d < 4; ++d)
        b[d] = exp((log(maxr[d]) - log(minr[d])) / 15.0);

    KConfig cfg;
    long long total = 0;
    for (int s = 0; s < 16; ++s) {
        long long res[4];
        for (int d = 0; d < 4; ++d)
            res[d] = (long long)ceil(minr[d] * pow(b[d], (double)s));
        long long raw = (res[0] + 1) * (res[1] + 1) * (res[2] + 1) * (res[3] + 1);
        long long p = (raw % 8 == 0) ? raw : ((raw + 7) / 8) * 8;
        if (p > MAXP) p = MAXP;
        int dense = (raw <= p) ? 1 : 0;

        Level& L = cfg.lv[s];
        L.rf0 = (float)res[0]; L.rf1 = (float)res[1];
        L.rf2 = (float)res[2]; L.rf3 = (float)res[3];
        L.s1 = (unsigned)(res[0] + 1);
        L.s2 = (unsigned)((res[0] + 1) * (res[1] + 1));
        L.s3 = (unsigned)((res[0] + 1) * (res[1] + 1) * (res[2] + 1));
        L.size = (unsigned)p;
        L.mask = (unsigned)(p - 1);
        L.offset = (int)total;
        if (dense)                      L.mode = 0;
        else if ((p & (p - 1)) == 0)    L.mode = 1;
        else                            L.mode = 2;
        total += p * 2;  // F = 2
    }
    return cfg;
}

// pattern check: modes = 0^k then 1^(16-k), with k < 4 (all dense in group 0)
static int split_ndense(const KConfig& cfg)
{
    int k = 0;
    while (k < 16 && cfg.lv[k].mode == 0) ++k;
    if (k >= 4) return -1;
    for (int s = k; s < 16; ++s)
        if (cfg.lv[s].mode != 1) return -1;
    return k;
}

extern "C" void kernel_launch(void* const* d_in, const int* in_sizes, int n_in,
                              void* d_out, int out_size)
{
    static KConfig cfg = build_cfg_host();
    static int ndense = split_ndense(cfg);

    const float4* xyzt = (const float4*)d_in[0];
    const float*  tab  = (const float*)d_in[1];
    float*        out  = (float*)d_out;

    int n = in_sizes[0] / 4;
    long long threads = 2LL * n;
    int blocks = (int)((threads + 255) / 256);

    if (ndense >= 0)
        hashenc_split_kernel<<<blocks, 256>>>(xyzt, tab, out, cfg, n, ndense);
    else
        hashenc_kernel<<<blocks, 256>>>(xyzt, tab, out, cfg, n);
}

// round 15
// speedup vs baseline: 1.0183x; 1.0183x over previous
#include <cuda_runtime.h>
#include <math.h>
#include <stdint.h>

// ---------------------------------------------------------------------------
// HashEncoderHyFluid, R13: R9 scheme (lane-pair cooperative gathers + 4-level
// batched coalesced float4 stores; 469us) with per-level shfl combines
// replaced by per-GROUP combines. Each lane buffers its own scaled partials:
// r[] = levels this lane stores, s[] = levels its partner stores. At a group
// boundary 4 shfl_xor deliver exactly the partner partials each lane needs
// (result_i = r_i + shfl(s_i)). SHFL+FADD warp-instructions halve (32->16),
// trimming MIO-pipe pressure that shares slots with the LDG stream.
// Arithmetic is bit-identical to R9 (same per-value add order).
// ---------------------------------------------------------------------------

struct Level {
    float    rf0, rf1, rf2, rf3;   // res as float32
    unsigned s1, s2, s3;           // dense strides
    unsigned mask;                 // size-1 (hashed pow2)
    unsigned size;
    int      offset;               // float offset into hash_table
    int      mode;                 // 0 dense, 1 hash+mask, 2 hash+mod
};
struct KConfig { Level lv[16]; };

#define HPRIME1 2654435761u
#define HPRIME2 805459861u
#define HPRIME3 3674653429u

__global__ __launch_bounds__(256)
void hashenc_kernel(const float4* __restrict__ xyzt,
                    const float*  __restrict__ tab,
                    float*        __restrict__ out,
                    KConfig cfg, int n)
{
    int tid = blockIdx.x * 256 + threadIdx.x;
    int q = tid >> 1;              // two lanes per query
    if (q >= n) return;
    const unsigned xb = (unsigned)(tid & 1);
    const unsigned amask = __activemask();   // pair lanes exit together

    float4 X = __ldg(&xyzt[q]);
    float4* orow = reinterpret_cast<float4*>(out + (size_t)q * 32);

    // per-lane partial buffers for the current 4-level group:
    // r0..r3 = partials of the 2 levels THIS lane stores (2 feats each)
    // s0..s3 = partials of the 2 levels the PARTNER lane stores
    float r0 = 0.f, r1 = 0.f, r2 = 0.f, r3 = 0.f;
    float s0 = 0.f, s1 = 0.f, s2 = 0.f, s3 = 0.f;

    #pragma unroll 1
    for (int s = 0; s < 16; ++s) {
        Level L = cfg.lv[s];

        float px = X.x * L.rf0, py = X.y * L.rf1, pz = X.z * L.rf2, pt = X.w * L.rf3;
        float gx = floorf(px),  gy = floorf(py),  gz = floorf(pz),  gt = floorf(pt);
        float fx = px - gx,     fy = py - gy,     fz = pz - gz,     ft = pt - gt;
        unsigned cx = (unsigned)(int)gx, cy = (unsigned)(int)gy;
        unsigned cz = (unsigned)(int)gz, ct = (unsigned)(int)gt;

        float wxs = xb ? fx : (1.f - fx);
        float wy0 = 1.f - fy, wz0 = 1.f - fz, wt0 = 1.f - ft;
        float wzt[4];
        wzt[0] = wz0 * wt0;  wzt[1] = fz * wt0;  wzt[2] = wz0 * ft;  wzt[3] = fz * ft;
        float wj[8];
        #pragma unroll
        for (int k = 0; k < 4; ++k) { wj[k] = wy0 * wzt[k]; wj[4 + k] = fy * wzt[k]; }

        unsigned bx = cx + xb;
        unsigned idx[8];
        if (L.mode == 0) {
            unsigned base0 = bx + cy * L.s1 + cz * L.s2 + ct * L.s3;
            idx[0] = base0;
            idx[1] = base0 + L.s2;
            idx[2] = base0 + L.s3;
            idx[3] = base0 + L.s2 + L.s3;
            #pragma unroll
            for (int k = 0; k < 4; ++k) idx[4 + k] = idx[k] + L.s1;
        } else if (L.mode == 1) {
            unsigned hy = cy * HPRIME1, hz = cz * HPRIME2, ht = ct * HPRIME3;
            unsigned msk = L.mask;
            unsigned rzt[4] = { hz ^ ht, (hz + HPRIME2) ^ ht,
                                hz ^ (ht + HPRIME3), (hz + HPRIME2) ^ (ht + HPRIME3) };
            #pragma unroll
            for (int k = 0; k < 4; ++k) {
                idx[k]     = (bx ^ hy             ^ rzt[k]) & msk;
                idx[4 + k] = (bx ^ (hy + HPRIME1) ^ rzt[k]) & msk;
            }
        } else {
            // generic mod fallback (never taken with current constants)
            unsigned hy = cy * HPRIME1, hz = cz * HPRIME2, ht = ct * HPRIME3;
            unsigned sz = L.size;
            unsigned rzt[4] = { hz ^ ht, (hz + HPRIME2) ^ ht,
                                hz ^ (ht + HPRIME3), (hz + HPRIME2) ^ (ht + HPRIME3) };
            #pragma unroll
            for (int k = 0; k < 4; ++k) {
                idx[k]     = (bx ^ hy             ^ rzt[k]) % sz;
                idx[4 + k] = (bx ^ (hy + HPRIME1) ^ rzt[k]) % sz;
            }
        }

        const float2* t2 = reinterpret_cast<const float2*>(tab) + (L.offset >> 1);
        float p0 = 0.f, p1 = 0.f;
        #pragma unroll
        for (int k = 0; k < 8; ++k) {
            float2 f = __ldg(t2 + idx[k]);    // pair lanes hit the same 128B line
            p0 += wj[k] * f.x;
            p1 += wj[k] * f.y;
        }
        p0 *= wxs;
        p1 *= wxs;

        // buffer partial: levels 4g,4g+1 stored by even lane (slot 2g),
        // levels 4g+2,4g+3 by odd lane (slot 2g+1).
        int j  = s & 3;
        bool to_r = xb ? (j >= 2) : (j < 2);   // goes to this lane's own half?
        int  k2   = (j < 2) ? j : (j - 2);     // 0 or 1 within either half
        if (to_r) {
            if (k2 == 0) { r0 = p0; r1 = p1; }
            else         { r2 = p0; r3 = p1; }
        } else {
            if (k2 == 0) { s0 = p0; s1 = p1; }
            else         { s2 = p0; s3 = p1; }
        }

        if (j == 3) {
            // 4 shfls per group: each lane receives exactly the partner
            // partials for the levels it stores.
            float4 v;
            v.x = r0 + __shfl_xor_sync(amask, s0, 1);
            v.y = r1 + __shfl_xor_sync(amask, s1, 1);
            v.z = r2 + __shfl_xor_sync(amask, s2, 1);
            v.w = r3 + __shfl_xor_sync(amask, s3, 1);
            orow[((s >> 2) << 1) + xb] = v;   // same 128B row, 1 coalesced wf
        }
    }
}

// ---------------------------------------------------------------------------
// Host-side config: mirrors reference build_config() op-for-op in float64.
// ---------------------------------------------------------------------------
static KConfig build_cfg_host()
{
    const double minr[4] = {16.0, 16.0, 16.0, 16.0};
    const double maxr[4] = {256.0, 256.0, 256.0, 128.0};
    const long long MAXP = 524288; // 2^19

    double b[4];
    for (int d = 0; d < 4; ++d)
        b[d] = exp((log(maxr[d]) - log(minr[d])) / 15.0);

    KConfig cfg;
    long long total = 0;
    for (int s = 0; s < 16; ++s) {
        long long res[4];
        for (int d = 0; d < 4; ++d)
            res[d] = (long long)ceil(minr[d] * pow(b[d], (double)s));
        long long raw = (res[0] + 1) * (res[1] + 1) * (res[2] + 1) * (res[3] + 1);
        long long p = (raw % 8 == 0) ? raw : ((raw + 7) / 8) * 8;
        if (p > MAXP) p = MAXP;
        int dense = (raw <= p) ? 1 : 0;

        Level& L = cfg.lv[s];
        L.rf0 = (float)res[0]; L.rf1 = (float)res[1];
        L.rf2 = (float)res[2]; L.rf3 = (float)res[3];
        L.s1 = (unsigned)(res[0] + 1);
        L.s2 = (unsigned)((res[0] + 1) * (res[1] + 1));
        L.s3 = (unsigned)((res[0] + 1) * (res[1] + 1) * (res[2] + 1));
        L.size = (unsigned)p;
        L.mask = (unsigned)(p - 1);
        L.offset = (int)total;
        if (dense)                      L.mode = 0;
        else if ((p & (p - 1)) == 0)    L.mode = 1;
        else                            L.mode = 2;
        total += p * 2;  // F = 2
    }
    return cfg;
}

extern "C" void kernel_launch(void* const* d_in, const int* in_sizes, int n_in,
                              void* d_out, int out_size)
{
    static KConfig cfg = build_cfg_host();

    const float4* xyzt = (const float4*)d_in[0];
    const float*  tab  = (const float*)d_in[1];
    float*        out  = (float*)d_out;

    int n = in_sizes[0] / 4;
    long long threads = 2LL * n;
    int blocks = (int)((threads + 255) / 256);
    hashenc_kernel<<<blocks, 256>>>(xyzt, tab, out, cfg, n);
}